// round 7
// baseline (speedup 1.0000x reference)
#include <cuda_runtime.h>
#include <cstdint>

// out[i,j] = | prod_k cos((x[i,k]-y[j,k])/2) |
//
// Per wire: cos((a-b)/2) = cos(a/2)cos(b/2) + sin(a/2)sin(b/2)
// Pair wires (2k,2k+1): t_2k*t_2k+1 = X.Y (4-dim dot),
//   X = (c0c1, c0s1, s0c1, s0s1), same for Y.
//
// All packed-f32x2 operands are fed DIRECTLY by LDS.128 (no register MOVs):
//   x smem: {w0,w0,w1,w1} / {w2,w2,w3,w3} float4 per row -> one broadcast
//           LDS.128 = two ready packed operands.
//   y smem: SoA per component; thread owns 4 contiguous columns -> one
//           LDS.128 per component = both packed column pairs.

#define D    16
#define KP   8
#define BM   128
#define BN   64
#define NT   256

#define FMA_X2(d, a, b, c) \
    asm("fma.rn.f32x2 %0, %1, %2, %3;" : "=l"(d) : "l"(a), "l"(b), "l"(c))
#define MUL_X2(d, a, b) \
    asm("mul.rn.f32x2 %0, %1, %2;" : "=l"(d) : "l"(a), "l"(b))

__global__ __launch_bounds__(NT, 3)
void qk_kernel(const float* __restrict__ x, const float* __restrict__ y,
               float* __restrict__ out, int n, int m) {
    __shared__ float4 sxd[KP][2][BM];   // 32 KB: {w0,w0,w1,w1},{w2,w2,w3,w3}
    __shared__ float  syp[KP][4][BN];   //  8 KB: SoA per component

    const int tid = threadIdx.x;
    const int bi  = blockIdx.y * BM;
    const int bj  = blockIdx.x * BN;

    // ---- Fill: threads 0..127 -> x rows, 128..191 -> y rows ----
    if (tid < BM + BN) {
        const bool isY  = (tid >= BM);
        const int  r    = isY ? (tid - BM) : tid;
        const int  gr   = (isY ? bj : bi) + r;
        const int  lim  = isY ? m : n;
        const float* src = isY ? y : x;

        float v[D];
        if (gr < lim) {
            const float4* p = reinterpret_cast<const float4*>(src + (size_t)gr * D);
            float4 a = p[0], b = p[1], c = p[2], d = p[3];
            v[0]=a.x;  v[1]=a.y;  v[2]=a.z;  v[3]=a.w;
            v[4]=b.x;  v[5]=b.y;  v[6]=b.z;  v[7]=b.w;
            v[8]=c.x;  v[9]=c.y;  v[10]=c.z; v[11]=c.w;
            v[12]=d.x; v[13]=d.y; v[14]=d.z; v[15]=d.w;
        } else {
#pragma unroll
            for (int k = 0; k < D; k++) v[k] = 0.0f;  // cos(0)=1 padding
        }

#pragma unroll
        for (int kp = 0; kp < KP; kp++) {
            float s0, c0, s1, c1;
            __sincosf(0.5f * v[2*kp + 0], &s0, &c0);
            __sincosf(0.5f * v[2*kp + 1], &s1, &c1);
            float w0 = c0*c1, w1 = c0*s1, w2 = s0*c1, w3 = s0*s1;
            if (isY) {
                syp[kp][0][r] = w0; syp[kp][1][r] = w1;
                syp[kp][2][r] = w2; syp[kp][3][r] = w3;
            } else {
                sxd[kp][0][r] = make_float4(w0, w0, w1, w1);
                sxd[kp][1][r] = make_float4(w2, w2, w3, w3);
            }
        }
    }
    __syncthreads();

    // ---- Main: 8 rows x 4 contiguous cols per thread ----
    // i = bi + ty + 16*ii (ii = 0..7);  j = bj + 4*tx + {0..3}
    const int tx = tid & 15;
    const int ty = tid >> 4;

    const uint64_t ONE2 = 0x3F8000003F800000ULL;
    uint64_t acc[8][2];
#pragma unroll
    for (int ii = 0; ii < 8; ii++) {
        acc[ii][0] = ONE2;
        acc[ii][1] = ONE2;
    }

#pragma unroll 2
    for (int kp = 0; kp < KP; kp++) {
        // y operands: one LDS.128 per component -> both packed pairs
        uint64_t yb[4][2];
#pragma unroll
        for (int c = 0; c < 4; c++) {
            float4 q = *reinterpret_cast<const float4*>(&syp[kp][c][4 * tx]);
            yb[c][0] = *reinterpret_cast<const uint64_t*>(&q.x);
            yb[c][1] = *reinterpret_cast<const uint64_t*>(&q.z);
        }

#pragma unroll
        for (int ii = 0; ii < 8; ii++) {
            const int row = ty + 16 * ii;
            float4 p0 = sxd[kp][0][row];   // {w0,w0,w1,w1}
            float4 p1 = sxd[kp][1][row];   // {w2,w2,w3,w3}
            uint64_t x0 = *reinterpret_cast<const uint64_t*>(&p0.x);
            uint64_t x1 = *reinterpret_cast<const uint64_t*>(&p0.z);
            uint64_t x2 = *reinterpret_cast<const uint64_t*>(&p1.x);
            uint64_t x3 = *reinterpret_cast<const uint64_t*>(&p1.z);
#pragma unroll
            for (int jj2 = 0; jj2 < 2; jj2++) {
                uint64_t t;
                MUL_X2(t, x0, yb[0][jj2]);
                FMA_X2(t, x1, yb[1][jj2], t);
                FMA_X2(t, x2, yb[2][jj2], t);
                FMA_X2(t, x3, yb[3][jj2], t);
                MUL_X2(acc[ii][jj2], acc[ii][jj2], t);
            }
        }
    }

    // ---- Store: packed abs + one STG.128 per row (4 adjacent cols) ----
    const uint64_t ABS2 = 0x7FFFFFFF7FFFFFFFULL;
    if (bi + BM <= n && bj + BN <= m) {
#pragma unroll
        for (int ii = 0; ii < 8; ii++) {
            uint64_t a0 = acc[ii][0] & ABS2;
            uint64_t a1 = acc[ii][1] & ABS2;
            float4 v;
            v.x = __uint_as_float((uint32_t)a0);
            v.y = __uint_as_float((uint32_t)(a0 >> 32));
            v.z = __uint_as_float((uint32_t)a1);
            v.w = __uint_as_float((uint32_t)(a1 >> 32));
            *reinterpret_cast<float4*>(
                out + (size_t)(bi + ty + 16 * ii) * m + (bj + 4 * tx)) = v;
        }
    } else {
#pragma unroll
        for (int ii = 0; ii < 8; ii++) {
            int gi = bi + ty + 16 * ii;
            if (gi >= n) continue;
#pragma unroll
            for (int jj2 = 0; jj2 < 2; jj2++) {
                uint64_t a = acc[ii][jj2] & ABS2;
                int gj = bj + 4 * tx + 2 * jj2;
                if (gj     < m) out[(size_t)gi * m + gj]     = __uint_as_float((uint32_t)a);
                if (gj + 1 < m) out[(size_t)gi * m + gj + 1] = __uint_as_float((uint32_t)(a >> 32));
            }
        }
    }
}

extern "C" void kernel_launch(void* const* d_in, const int* in_sizes, int n_in,
                              void* d_out, int out_size) {
    const float* x = (const float*)d_in[0];
    const float* y = (const float*)d_in[1];
    float* out = (float*)d_out;
    int n = in_sizes[0] / D;
    int m = in_sizes[1] / D;

    dim3 block(NT);
    dim3 grid((m + BN - 1) / BN, (n + BM - 1) / BM);
    qk_kernel<<<grid, block>>>(x, y, out, n, m);
}